// round 1
// baseline (speedup 1.0000x reference)
#include <cuda_runtime.h>

// Problem constants (fixed by the dataset): qkv (B,S,3,H,D) fp32
#define B_  2
#define S_  2048
#define H_  16
#define D_  64
#define QKV_LD (3 * H_ * D_)   // 3072 floats between consecutive s rows
#define TS  64                 // tile size
#define PAD 65                 // smem padding to dodge bank conflicts
#define NT  (S_ / TS)          // 32 tiles along S

// Scratch (allocation-free rule: __device__ globals)
// g_a holds a1, then overwritten in-place with a = 2*a1 - a2 (lower-tri tiles only)
__device__ float g_a [B_ * H_ * S_ * S_];   // 536 MB
__device__ float g_o2[B_ * H_ * S_ * D_];   // 16 MB

// ---------------------------------------------------------------------------
// Load a 64x64 fp32 tile (row-major, leading dim ld) into smem [TS][PAD].
// 256 threads, float4 global reads, scalar smem writes.
// ---------------------------------------------------------------------------
__device__ __forceinline__ void load_tile(const float* __restrict__ g, int ld,
                                          float sm[TS][PAD], int tx, int ty) {
#pragma unroll
    for (int r = 0; r < 4; r++) {
        int row = ty + r * 16;
        float4 v = *reinterpret_cast<const float4*>(g + (size_t)row * ld + tx * 4);
        sm[row][tx * 4 + 0] = v.x;
        sm[row][tx * 4 + 1] = v.y;
        sm[row][tx * 4 + 2] = v.z;
        sm[row][tx * 4 + 3] = v.w;
    }
}

// ===========================================================================
// K1: a1[bh, t, s] = tril( q[t,:] . k[s,:] )   (only lower-triangle tiles)
// A = q (m-major, k-dim = d), B = k (n-major, k-dim = d)
// ===========================================================================
__global__ __launch_bounds__(256) void k_qk(const float* __restrict__ qkv) {
    int st = blockIdx.x, tt = blockIdx.y, bh = blockIdx.z;
    if (st > tt) return;
    int b = bh >> 4, h = bh & 15;
    const float* qb = qkv + (size_t)b * S_ * QKV_LD + h * D_;
    const float* kb = qb + H_ * D_;

    __shared__ float As[TS][PAD], Bs[TS][PAD];
    int tid = threadIdx.x, tx = tid & 15, ty = tid >> 4;

    load_tile(qb + (size_t)tt * TS * QKV_LD, QKV_LD, As, tx, ty);
    load_tile(kb + (size_t)st * TS * QKV_LD, QKV_LD, Bs, tx, ty);
    __syncthreads();

    float c[4][4] = {};
#pragma unroll 16
    for (int kk = 0; kk < TS; kk++) {
        float av[4], bv[4];
#pragma unroll
        for (int i = 0; i < 4; i++) av[i] = As[ty * 4 + i][kk];
#pragma unroll
        for (int j = 0; j < 4; j++) bv[j] = Bs[tx * 4 + j][kk];
#pragma unroll
        for (int i = 0; i < 4; i++)
#pragma unroll
            for (int j = 0; j < 4; j++) c[i][j] += av[i] * bv[j];
    }

    float* cb = g_a + ((size_t)bh * S_ + tt * TS) * S_ + st * TS;
#pragma unroll
    for (int i = 0; i < 4; i++) {
        int row = ty * 4 + i;
        if (st == tt) {
#pragma unroll
            for (int j = 0; j < 4; j++)
                if (tx * 4 + j > row) c[i][j] = 0.0f;
        }
        *reinterpret_cast<float4*>(cb + (size_t)row * S_ + tx * 4) =
            make_float4(c[i][0], c[i][1], c[i][2], c[i][3]);
    }
}

// ===========================================================================
// K2: o2[bh, t, d] = sum_{s<=t} a1[t,s] * k[s,d]
// A = a1 (m-major, k-dim = s), B = k (k-major rows: Bs[k][n])
// ===========================================================================
__global__ __launch_bounds__(256) void k_o2(const float* __restrict__ qkv) {
    int tt = blockIdx.x, bh = blockIdx.y;
    int b = bh >> 4, h = bh & 15;
    const float* kb = qkv + (size_t)b * S_ * QKV_LD + H_ * D_ + h * D_;

    __shared__ float As[TS][PAD], Bs[TS][PAD];
    int tid = threadIdx.x, tx = tid & 15, ty = tid >> 4;

    float c[4][4] = {};
    const float* arow = g_a + ((size_t)bh * S_ + tt * TS) * S_;

    for (int st = 0; st <= tt; st++) {
        load_tile(arow + st * TS, S_, As, tx, ty);
        load_tile(kb + (size_t)st * TS * QKV_LD, QKV_LD, Bs, tx, ty);
        __syncthreads();
#pragma unroll 16
        for (int kk = 0; kk < TS; kk++) {
            float av[4], bv[4];
#pragma unroll
            for (int i = 0; i < 4; i++) av[i] = As[ty * 4 + i][kk];
#pragma unroll
            for (int j = 0; j < 4; j++) bv[j] = Bs[kk][tx * 4 + j];
#pragma unroll
            for (int i = 0; i < 4; i++)
#pragma unroll
                for (int j = 0; j < 4; j++) c[i][j] += av[i] * bv[j];
        }
        __syncthreads();
    }

    float* ob = g_o2 + ((size_t)bh * S_ + tt * TS) * D_;
#pragma unroll
    for (int i = 0; i < 4; i++) {
        int row = ty * 4 + i;
        *reinterpret_cast<float4*>(ob + (size_t)row * D_ + tx * 4) =
            make_float4(c[i][0], c[i][1], c[i][2], c[i][3]);
    }
}

// ===========================================================================
// K3: a[t,s] = 2*a1[t,s] - tril(o2[t,:] . k[s,:])     (in place into g_a)
// A = o2 (m-major, k-dim = d), B = k (n-major, k-dim = d)
// ===========================================================================
__global__ __launch_bounds__(256) void k_a2(const float* __restrict__ qkv) {
    int st = blockIdx.x, tt = blockIdx.y, bh = blockIdx.z;
    if (st > tt) return;
    int b = bh >> 4, h = bh & 15;
    const float* kb = qkv + (size_t)b * S_ * QKV_LD + H_ * D_ + h * D_;

    __shared__ float As[TS][PAD], Bs[TS][PAD];
    int tid = threadIdx.x, tx = tid & 15, ty = tid >> 4;

    load_tile(g_o2 + ((size_t)bh * S_ + tt * TS) * D_, D_, As, tx, ty);
    load_tile(kb + (size_t)st * TS * QKV_LD, QKV_LD, Bs, tx, ty);
    __syncthreads();

    float c[4][4] = {};
#pragma unroll 16
    for (int kk = 0; kk < TS; kk++) {
        float av[4], bv[4];
#pragma unroll
        for (int i = 0; i < 4; i++) av[i] = As[ty * 4 + i][kk];
#pragma unroll
        for (int j = 0; j < 4; j++) bv[j] = Bs[tx * 4 + j][kk];
#pragma unroll
        for (int i = 0; i < 4; i++)
#pragma unroll
            for (int j = 0; j < 4; j++) c[i][j] += av[i] * bv[j];
    }

    float* ab = g_a + ((size_t)bh * S_ + tt * TS) * S_ + st * TS;
#pragma unroll
    for (int i = 0; i < 4; i++) {
        int row = ty * 4 + i;
        float4 a1v = *reinterpret_cast<const float4*>(ab + (size_t)row * S_ + tx * 4);
        float4 r;
        r.x = 2.0f * a1v.x - c[i][0];
        r.y = 2.0f * a1v.y - c[i][1];
        r.z = 2.0f * a1v.z - c[i][2];
        r.w = 2.0f * a1v.w - c[i][3];
        if (st == tt) {   // inside diagonal tile: zero strictly-upper part
            if (tx * 4 + 0 > row) r.x = 0.0f;
            if (tx * 4 + 1 > row) r.y = 0.0f;
            if (tx * 4 + 2 > row) r.z = 0.0f;
            if (tx * 4 + 3 > row) r.w = 0.0f;
        }
        *reinterpret_cast<float4*>(ab + (size_t)row * S_ + tx * 4) = r;
    }
}

// ===========================================================================
// K4: out[b, t, h, d] = sum_{s<=t} a[t,s] * v[s,d]
// A = a (m-major, k-dim = s), B = v (k-major rows)
// ===========================================================================
__global__ __launch_bounds__(256) void k_out(const float* __restrict__ qkv,
                                             float* __restrict__ out) {
    int tt = blockIdx.x, bh = blockIdx.y;
    int b = bh >> 4, h = bh & 15;
    const float* vb = qkv + (size_t)b * S_ * QKV_LD + 2 * H_ * D_ + h * D_;

    __shared__ float As[TS][PAD], Bs[TS][PAD];
    int tid = threadIdx.x, tx = tid & 15, ty = tid >> 4;

    float c[4][4] = {};
    const float* arow = g_a + ((size_t)bh * S_ + tt * TS) * S_;

    for (int st = 0; st <= tt; st++) {
        load_tile(arow + st * TS, S_, As, tx, ty);
        load_tile(vb + (size_t)st * TS * QKV_LD, QKV_LD, Bs, tx, ty);
        __syncthreads();
#pragma unroll 16
        for (int kk = 0; kk < TS; kk++) {
            float av[4], bv[4];
#pragma unroll
            for (int i = 0; i < 4; i++) av[i] = As[ty * 4 + i][kk];
#pragma unroll
            for (int j = 0; j < 4; j++) bv[j] = Bs[kk][tx * 4 + j];
#pragma unroll
            for (int i = 0; i < 4; i++)
#pragma unroll
                for (int j = 0; j < 4; j++) c[i][j] += av[i] * bv[j];
        }
        __syncthreads();
    }

    // out layout: (B, S, H, D)
#pragma unroll
    for (int i = 0; i < 4; i++) {
        int row = ty * 4 + i;
        float* ob = out + ((size_t)(b * S_ + tt * TS + row)) * (H_ * D_) + h * D_;
        *reinterpret_cast<float4*>(ob + tx * 4) =
            make_float4(c[i][0], c[i][1], c[i][2], c[i][3]);
    }
}

// ===========================================================================
extern "C" void kernel_launch(void* const* d_in, const int* in_sizes, int n_in,
                              void* d_out, int out_size) {
    const float* qkv = (const float*)d_in[0];
    float* out = (float*)d_out;

    dim3 blk(256);
    dim3 grid_tri(NT, NT, B_ * H_);   // (s_tile, t_tile, bh); s>t tiles exit early
    dim3 grid_row(NT, B_ * H_);       // (t_tile, bh)

    k_qk <<<grid_tri, blk>>>(qkv);
    k_o2 <<<grid_row, blk>>>(qkv);
    k_a2 <<<grid_tri, blk>>>(qkv);
    k_out<<<grid_row, blk>>>(qkv, out);
}